// round 6
// baseline (speedup 1.0000x reference)
#include <cuda_runtime.h>
#include <math.h>
#include <stdint.h>

// Multiresolution hash-grid encoding (Instant-NGP style), two-phase:
//
//  Phase 1 (build): for coarse levels 0..11, materialize a DENSE grid where
//  entry (cx,cy,cz) = float4( v(cx,cy,cz), v(cx+1,cy,cz) ) — the x-corner
//  pair packed into one 16B-aligned value. 1.18M cells, ~19MB, L2-resident.
//
//  Phase 2 (main): one thread per (point, level).
//   - level < 12: 4 float4 gathers from the dense grid (each returns BOTH
//     x-corners of one (y,z) group) -> 4 loads instead of avg 6.
//   - level >= 12: hash path with even-pair float4 merge + predicated odd load.
//  Output row = 16 contiguous float2 -> coalesced stores.

#define N_LEVELS   16
#define N_DENSE    12
#define LOG2_T     19
#define T_MASK     ((1u << LOG2_T) - 1u)
#define P1         2654435761u
#define P2         805459861u

// Dense pair-grid scratch: levels 0..11 need ~1.18M float4; overallocate.
#define G_CAP 2000000
__device__ float4 g_dense[G_CAP];   // 32 MB, zero-init .bss (no cubin bloat)

struct Params {
    float resf[N_LEVELS];
    int   off[N_DENSE];     // float4 offset of each dense level
};

// ---------------------------------------------------------------- build ----
__global__ __launch_bounds__(256) void build_dense_kernel(
    const float2* __restrict__ table, Params p)
{
    const int l = blockIdx.y;
    const int r = (int)p.resf[l];
    const int W = r, H = r + 1;
    const int cells = W * H * H;
    const int i = blockIdx.x * 256 + threadIdx.x;
    if (i >= cells) return;

    const int cx = i % W;
    const int t  = i / W;
    const int cy = t % H;
    const int cz = t / H;

    const unsigned g  = ((unsigned)cy * P1) ^ ((unsigned)cz * P2);
    const unsigned h0 = ((unsigned)cx ^ g) & T_MASK;
    const unsigned h1 = ((unsigned)(cx + 1) ^ g) & T_MASK;

    const float2 a = __ldg(&table[h0]);
    const float2 b = __ldg(&table[h1]);
    g_dense[p.off[l] + i] = make_float4(a.x, a.y, b.x, b.y);
}

// ----------------------------------------------------------------- main ----
__global__ __launch_bounds__(256) void hashgrid_kernel(
    const float* __restrict__ x,        // [N,3]
    const float2* __restrict__ table,   // [T] float2
    float2* __restrict__ out,           // [N,16] float2
    Params p, int N)
{
    int gid = blockIdx.x * 256 + threadIdx.x;
    int n = gid >> 4;
    if (n >= N) return;
    int l = gid & 15;

    const float px = __ldg(&x[n * 3 + 0]);
    const float py = __ldg(&x[n * 3 + 1]);
    const float pz = __ldg(&x[n * 3 + 2]);

    const float res = p.resf[l];
    const float sx = px * res;
    const float sy = py * res;
    const float sz = pz * res;

    float2 v000, v100, v010, v001, v110, v101, v011, v111;
    float dx, dy, dz;

    if (l < N_DENSE) {
        // ---- dense pair-grid path: 4 float4 gathers, x-pair packed ----
        const int r = (int)res;
        const int W = r, H = r + 1;

        int ix0 = (int)floorf(sx);
        int iy0 = (int)floorf(sy);
        int iz0 = (int)floorf(sz);
        // clamp: if s hit the upper edge exactly, shift cell down, d becomes 1.0
        // (weight-0 corner swap — identical result to reference)
        if (ix0 > W - 1) ix0 = W - 1;
        if (iy0 > H - 2) iy0 = H - 2;
        if (iz0 > H - 2) iz0 = H - 2;

        dx = sx - (float)ix0;
        dy = sy - (float)iy0;
        dz = sz - (float)iz0;

        const float4* __restrict__ G = g_dense + p.off[l];
        const int i00 = (iz0 * H + iy0) * W + ix0;
        const int i10 = i00 + W;          // y+1
        const int i01 = i00 + W * H;      // z+1
        const int i11 = i01 + W;

        const float4 q00 = __ldg(&G[i00]);
        const float4 q10 = __ldg(&G[i10]);
        const float4 q01 = __ldg(&G[i01]);
        const float4 q11 = __ldg(&G[i11]);

        v000 = make_float2(q00.x, q00.y);  v100 = make_float2(q00.z, q00.w);
        v010 = make_float2(q10.x, q10.y);  v110 = make_float2(q10.z, q10.w);
        v001 = make_float2(q01.x, q01.y);  v101 = make_float2(q01.z, q01.w);
        v011 = make_float2(q11.x, q11.y);  v111 = make_float2(q11.z, q11.w);
    } else {
        // ---- hash path (fine levels): even-pair float4 merge ----
        const float fx = floorf(sx);
        const float fy = floorf(sy);
        const float fz = floorf(sz);
        const int ix0 = (int)fx, iy0 = (int)fy, iz0 = (int)fz;

        dx = sx - fx;
        dy = sy - fy;
        dz = sz - fz;

        const unsigned x0u = (unsigned)ix0;
        const unsigned hy0 = (unsigned)iy0 * P1;
        const unsigned hy1 = (unsigned)(iy0 + 1) * P1;
        const unsigned hz0 = (unsigned)iz0 * P2;
        const unsigned hz1 = (unsigned)(iz0 + 1) * P2;

        const unsigned g00 = hy0 ^ hz0;
        const unsigned g10 = hy1 ^ hz0;
        const unsigned g01 = hy0 ^ hz1;
        const unsigned g11 = hy1 ^ hz1;

        const unsigned h000 = (x0u ^ g00) & T_MASK;
        const unsigned h010 = (x0u ^ g10) & T_MASK;
        const unsigned h001 = (x0u ^ g01) & T_MASK;
        const unsigned h011 = (x0u ^ g11) & T_MASK;

        const unsigned x1u  = x0u + 1u;
        const unsigned h100 = (x1u ^ g00) & T_MASK;
        const unsigned h110 = (x1u ^ g10) & T_MASK;
        const unsigned h101 = (x1u ^ g01) & T_MASK;
        const unsigned h111 = (x1u ^ g11) & T_MASK;

        const bool xeven = (x0u & 1u) == 0u;

        const float4 q00 = __ldg((const float4*)&table[h000 & ~1u]);
        const float4 q10 = __ldg((const float4*)&table[h010 & ~1u]);
        const float4 q01 = __ldg((const float4*)&table[h001 & ~1u]);
        const float4 q11 = __ldg((const float4*)&table[h011 & ~1u]);

        float2 e00, e10, e01, e11;
        if (!xeven) {
            e00 = __ldg(&table[h100]);
            e10 = __ldg(&table[h110]);
            e01 = __ldg(&table[h101]);
            e11 = __ldg(&table[h111]);
        }

        const float2 q00lo = make_float2(q00.x, q00.y), q00hi = make_float2(q00.z, q00.w);
        const float2 q10lo = make_float2(q10.x, q10.y), q10hi = make_float2(q10.z, q10.w);
        const float2 q01lo = make_float2(q01.x, q01.y), q01hi = make_float2(q01.z, q01.w);
        const float2 q11lo = make_float2(q11.x, q11.y), q11hi = make_float2(q11.z, q11.w);

        const bool p00 = (h000 & 1u), p10 = (h010 & 1u), p01 = (h001 & 1u), p11 = (h011 & 1u);

        v000 = p00 ? q00hi : q00lo;
        v010 = p10 ? q10hi : q10lo;
        v001 = p01 ? q01hi : q01lo;
        v011 = p11 ? q11hi : q11lo;

        v100 = xeven ? (p00 ? q00lo : q00hi) : e00;
        v110 = xeven ? (p10 ? q10lo : q10hi) : e10;
        v101 = xeven ? (p01 ? q01lo : q01hi) : e01;
        v111 = xeven ? (p11 ? q11lo : q11hi) : e11;
    }

    const float wx0 = 1.0f - dx, wx1 = dx;
    const float wy0 = 1.0f - dy, wy1 = dy;
    const float wz0 = 1.0f - dz, wz1 = dz;

    float a00x = v000.x * wx0 + v100.x * wx1;
    float a00y = v000.y * wx0 + v100.y * wx1;
    float a10x = v010.x * wx0 + v110.x * wx1;
    float a10y = v010.y * wx0 + v110.y * wx1;
    float a01x = v001.x * wx0 + v101.x * wx1;
    float a01y = v001.y * wx0 + v101.y * wx1;
    float a11x = v011.x * wx0 + v111.x * wx1;
    float a11y = v011.y * wx0 + v111.y * wx1;

    float b0x = a00x * wy0 + a10x * wy1;
    float b0y = a00y * wy0 + a10y * wy1;
    float b1x = a01x * wy0 + a11x * wy1;
    float b1y = a01y * wy0 + a11y * wy1;

    float2 rr;
    rr.x = b0x * wz0 + b1x * wz1;
    rr.y = b0y * wz0 + b1y * wz1;

    out[gid] = rr;
}

// --------------------------------------------------------------- launch ----
extern "C" void kernel_launch(void* const* d_in, const int* in_sizes, int n_in,
                              void* d_out, int out_size)
{
    const float*  x     = (const float*)d_in[0];
    const float2* table = (const float2*)d_in[1];
    float2*       out   = (float2*)d_out;

    const int N = in_sizes[0] / 3;

    Params p;
    int max_cells = 0;
    {
        const double growth = exp((log(128.0) - log(16.0)) / (double)(N_LEVELS - 1));
        int off = 0;
        for (int l = 0; l < N_LEVELS; ++l) {
            const int r = (int)floor(16.0 * pow(growth, (double)l));
            p.resf[l] = (float)r;
            if (l < N_DENSE) {
                p.off[l] = off;
                const int cells = r * (r + 1) * (r + 1);
                if (cells > max_cells) max_cells = cells;
                off += cells;
            }
        }
        // off must be <= G_CAP (is ~1.18M for these resolutions)
    }

    // Phase 1: build dense pair-grids for levels 0..11
    {
        dim3 grid((max_cells + 255) / 256, N_DENSE);
        build_dense_kernel<<<grid, 256>>>(table, p);
    }

    // Phase 2: main encoding
    {
        const long long total = (long long)N * N_LEVELS;
        const int blocks = (int)((total + 255) / 256);
        hashgrid_kernel<<<blocks, 256>>>(x, table, out, p, N);
    }
}

// round 8
// speedup vs baseline: 1.5990x; 1.5990x over previous
#include <cuda_runtime.h>
#include <math.h>
#include <stdint.h>

// Multiresolution hash-grid encoding, spatially-sorted gather version.
//
// Pipeline (all graph-capturable, scratch in __device__ globals):
//  K0 zero_hist    : clear 32768-bucket histogram
//  K1 hist         : Morton bucket (res 32) per point, atomic histogram
//  K2 scan         : exclusive scan -> bucket cursors (single block)
//  K3 scatter      : permutation: sorted position -> point index
//  K4 main         : one THREAD per point (warp = 32 spatially adjacent
//                    points), loop over 16 levels. Same-cell lanes hash to
//                    identical table lines -> L1 merges them into one
//                    wavefront. Row buffered in registers, stored as 8
//                    float4 (full 128B row per point).
//
// Hash merge trick retained: prime on x is 1, so for even x0 the x-pair
// (x0, x0+1) lives in one 16B-aligned float4 of the table.

#define N_LEVELS 16
#define LOG2_T   19
#define T_MASK   ((1u << LOG2_T) - 1u)
#define P1       2654435761u
#define P2       805459861u

#define SORT_RES   32
#define N_BUCKETS  (SORT_RES * SORT_RES * SORT_RES)   // 32768
#define MAX_N      1100000

__device__ unsigned g_hist[N_BUCKETS];
__device__ unsigned g_cursor[N_BUCKETS];
__device__ int      g_perm[MAX_N];

struct Params { float resf[N_LEVELS]; };

// ------------------------------------------------------------------ morton
__device__ __forceinline__ unsigned expand_bits(unsigned v) {
    v = (v * 0x00010001u) & 0xFF0000FFu;
    v = (v * 0x00000101u) & 0x0F00F00Fu;
    v = (v * 0x00000011u) & 0xC30C30C3u;
    v = (v * 0x00000005u) & 0x49249249u;
    return v;
}

__device__ __forceinline__ unsigned bucket_of(float px, float py, float pz) {
    int cx = (int)(px * (float)SORT_RES);
    int cy = (int)(py * (float)SORT_RES);
    int cz = (int)(pz * (float)SORT_RES);
    cx = min(max(cx, 0), SORT_RES - 1);
    cy = min(max(cy, 0), SORT_RES - 1);
    cz = min(max(cz, 0), SORT_RES - 1);
    return expand_bits((unsigned)cx)
         | (expand_bits((unsigned)cy) << 1)
         | (expand_bits((unsigned)cz) << 2);
}

// ---------------------------------------------------------------- kernels
__global__ void zero_hist_kernel() {
    int i = blockIdx.x * blockDim.x + threadIdx.x;
    if (i < N_BUCKETS) g_hist[i] = 0u;
}

__global__ __launch_bounds__(256) void hist_kernel(const float* __restrict__ x, int N) {
    int n = blockIdx.x * 256 + threadIdx.x;
    if (n >= N) return;
    unsigned b = bucket_of(x[n * 3 + 0], x[n * 3 + 1], x[n * 3 + 2]);
    atomicAdd(&g_hist[b], 1u);
}

__global__ __launch_bounds__(1024) void scan_kernel() {
    __shared__ unsigned partial[1024];
    const int t = threadIdx.x;
    unsigned local[32];
    unsigned s = 0;
    #pragma unroll
    for (int j = 0; j < 32; ++j) { local[j] = g_hist[t * 32 + j]; s += local[j]; }
    partial[t] = s;
    __syncthreads();
    // Hillis-Steele inclusive scan over 1024 partials
    for (int d = 1; d < 1024; d <<= 1) {
        unsigned v = (t >= d) ? partial[t - d] : 0u;
        __syncthreads();
        partial[t] += v;
        __syncthreads();
    }
    unsigned run = (t > 0) ? partial[t - 1] : 0u;
    #pragma unroll
    for (int j = 0; j < 32; ++j) { g_cursor[t * 32 + j] = run; run += local[j]; }
}

__global__ __launch_bounds__(256) void scatter_kernel(const float* __restrict__ x, int N) {
    int n = blockIdx.x * 256 + threadIdx.x;
    if (n >= N) return;
    unsigned b = bucket_of(x[n * 3 + 0], x[n * 3 + 1], x[n * 3 + 2]);
    unsigned pos = atomicAdd(&g_cursor[b], 1u);
    g_perm[pos] = n;
}

// ------------------------------------------------------------------- main
__global__ __launch_bounds__(256) void hashgrid_kernel(
    const float* __restrict__ x,        // [N,3]
    const float2* __restrict__ table,   // [T] float2
    float4* __restrict__ out,           // [N,16] float2 viewed as [N,8] float4
    Params p, int N)
{
    const int i = blockIdx.x * 256 + threadIdx.x;
    if (i >= N) return;
    const int n = g_perm[i];

    const float px = __ldg(&x[n * 3 + 0]);
    const float py = __ldg(&x[n * 3 + 1]);
    const float pz = __ldg(&x[n * 3 + 2]);

    float2 acc[N_LEVELS];

    #pragma unroll
    for (int l = 0; l < N_LEVELS; ++l) {
        const float res = p.resf[l];
        const float sx = px * res;
        const float sy = py * res;
        const float sz = pz * res;

        const float fx = floorf(sx);
        const float fy = floorf(sy);
        const float fz = floorf(sz);

        const float dx = sx - fx;
        const float dy = sy - fy;
        const float dz = sz - fz;

        const unsigned x0u = (unsigned)(int)fx;
        const unsigned hy0 = (unsigned)(int)fy * P1;
        const unsigned hy1 = hy0 + P1;
        const unsigned hz0 = (unsigned)(int)fz * P2;
        const unsigned hz1 = hz0 + P2;

        const unsigned g00 = hy0 ^ hz0;
        const unsigned g10 = hy1 ^ hz0;
        const unsigned g01 = hy0 ^ hz1;
        const unsigned g11 = hy1 ^ hz1;

        const unsigned h000 = (x0u ^ g00) & T_MASK;
        const unsigned h010 = (x0u ^ g10) & T_MASK;
        const unsigned h001 = (x0u ^ g01) & T_MASK;
        const unsigned h011 = (x0u ^ g11) & T_MASK;

        const unsigned x1u  = x0u + 1u;
        const unsigned h100 = (x1u ^ g00) & T_MASK;
        const unsigned h110 = (x1u ^ g10) & T_MASK;
        const unsigned h101 = (x1u ^ g01) & T_MASK;
        const unsigned h111 = (x1u ^ g11) & T_MASK;

        const bool xeven = (x0u & 1u) == 0u;

        // 4 float4 loads always cover the x0 corners (and x1 when x0 even)
        const float4 q00 = __ldg((const float4*)&table[h000 & ~1u]);
        const float4 q10 = __ldg((const float4*)&table[h010 & ~1u]);
        const float4 q01 = __ldg((const float4*)&table[h001 & ~1u]);
        const float4 q11 = __ldg((const float4*)&table[h011 & ~1u]);

        float2 e00, e10, e01, e11;
        if (!xeven) {
            e00 = __ldg(&table[h100]);
            e10 = __ldg(&table[h110]);
            e01 = __ldg(&table[h101]);
            e11 = __ldg(&table[h111]);
        }

        const float2 q00lo = make_float2(q00.x, q00.y), q00hi = make_float2(q00.z, q00.w);
        const float2 q10lo = make_float2(q10.x, q10.y), q10hi = make_float2(q10.z, q10.w);
        const float2 q01lo = make_float2(q01.x, q01.y), q01hi = make_float2(q01.z, q01.w);
        const float2 q11lo = make_float2(q11.x, q11.y), q11hi = make_float2(q11.z, q11.w);

        const bool p00 = (h000 & 1u), p10 = (h010 & 1u), p01 = (h001 & 1u), p11 = (h011 & 1u);

        const float2 v000 = p00 ? q00hi : q00lo;
        const float2 v010 = p10 ? q10hi : q10lo;
        const float2 v001 = p01 ? q01hi : q01lo;
        const float2 v011 = p11 ? q11hi : q11lo;

        const float2 v100 = xeven ? (p00 ? q00lo : q00hi) : e00;
        const float2 v110 = xeven ? (p10 ? q10lo : q10hi) : e10;
        const float2 v101 = xeven ? (p01 ? q01lo : q01hi) : e01;
        const float2 v111 = xeven ? (p11 ? q11lo : q11hi) : e11;

        const float wx0 = 1.0f - dx, wx1 = dx;
        const float wy0 = 1.0f - dy, wy1 = dy;
        const float wz0 = 1.0f - dz, wz1 = dz;

        float a00x = v000.x * wx0 + v100.x * wx1;
        float a00y = v000.y * wx0 + v100.y * wx1;
        float a10x = v010.x * wx0 + v110.x * wx1;
        float a10y = v010.y * wx0 + v110.y * wx1;
        float a01x = v001.x * wx0 + v101.x * wx1;
        float a01y = v001.y * wx0 + v101.y * wx1;
        float a11x = v011.x * wx0 + v111.x * wx1;
        float a11y = v011.y * wx0 + v111.y * wx1;

        float b0x = a00x * wy0 + a10x * wy1;
        float b0y = a00y * wy0 + a10y * wy1;
        float b1x = a01x * wy0 + a11x * wy1;
        float b1y = a01y * wy0 + a11y * wy1;

        acc[l].x = b0x * wz0 + b1x * wz1;
        acc[l].y = b0y * wz0 + b1y * wz1;
    }

    // Store full 128B row as 8 float4 (row base 16B-aligned).
    float4* row = out + (size_t)n * 8;
    #pragma unroll
    for (int j = 0; j < 8; ++j) {
        row[j] = make_float4(acc[2 * j].x, acc[2 * j].y,
                             acc[2 * j + 1].x, acc[2 * j + 1].y);
    }
}

// ----------------------------------------------------------------- launch
extern "C" void kernel_launch(void* const* d_in, const int* in_sizes, int n_in,
                              void* d_out, int out_size)
{
    const float*  x     = (const float*)d_in[0];
    const float2* table = (const float2*)d_in[1];
    float4*       out   = (float4*)d_out;

    const int N = in_sizes[0] / 3;

    Params p;
    {
        const double growth = exp((log(128.0) - log(16.0)) / (double)(N_LEVELS - 1));
        for (int l = 0; l < N_LEVELS; ++l)
            p.resf[l] = (float)floor(16.0 * pow(growth, (double)l));
    }

    const int pb = (N + 255) / 256;

    zero_hist_kernel<<<(N_BUCKETS + 255) / 256, 256>>>();
    hist_kernel<<<pb, 256>>>(x, N);
    scan_kernel<<<1, 1024>>>();
    scatter_kernel<<<pb, 256>>>(x, N);
    hashgrid_kernel<<<pb, 256>>>(x, table, out, p, N);
}

// round 9
// speedup vs baseline: 1.6662x; 1.0420x over previous
#include <cuda_runtime.h>
#include <math.h>
#include <stdint.h>

// Multiresolution hash-grid encoding, spatially-sorted gather version (v2).
//
// Pipeline (graph-capturable, scratch in __device__ globals):
//  K0 zero_hist : clear 32768-bucket histogram
//  K1 hist      : Morton bucket (res 32) per point; atomicAdd returns the
//                 point's RANK within its bucket -> store (bucket, rank)
//  K2 scan      : exclusive scan of histogram -> bucket bases (single block)
//  K3 scatter   : pos = base[bucket] + rank (NO atomics); write sorted
//                 float4(x,y,z, idx) to g_xs[pos]
//  K4 main      : one thread per sorted point (warp = 32 spatially adjacent
//                 points). Coalesced float4 coord load. 16-level loop with
//                 x-pair float4 hash merge. Row buffered in registers,
//                 stored as 8 float4 (full 128B row).

#define N_LEVELS 16
#define LOG2_T   19
#define T_MASK   ((1u << LOG2_T) - 1u)
#define P1       2654435761u
#define P2       805459861u

#define SORT_RES   32
#define N_BUCKETS  (SORT_RES * SORT_RES * SORT_RES)   // 32768
#define MAX_N      1100000

__device__ unsigned g_hist[N_BUCKETS];
__device__ unsigned g_base[N_BUCKETS];
__device__ unsigned g_bucket[MAX_N];
__device__ unsigned g_rank[MAX_N];
__device__ float4   g_xs[MAX_N];      // sorted (x,y,z, idx-as-bits)

struct Params { float resf[N_LEVELS]; };

// ------------------------------------------------------------------ morton
__device__ __forceinline__ unsigned expand_bits(unsigned v) {
    v = (v * 0x00010001u) & 0xFF0000FFu;
    v = (v * 0x00000101u) & 0x0F00F00Fu;
    v = (v * 0x00000011u) & 0xC30C30C3u;
    v = (v * 0x00000005u) & 0x49249249u;
    return v;
}

__device__ __forceinline__ unsigned bucket_of(float px, float py, float pz) {
    int cx = (int)(px * (float)SORT_RES);
    int cy = (int)(py * (float)SORT_RES);
    int cz = (int)(pz * (float)SORT_RES);
    cx = min(max(cx, 0), SORT_RES - 1);
    cy = min(max(cy, 0), SORT_RES - 1);
    cz = min(max(cz, 0), SORT_RES - 1);
    return expand_bits((unsigned)cx)
         | (expand_bits((unsigned)cy) << 1)
         | (expand_bits((unsigned)cz) << 2);
}

// ---------------------------------------------------------------- kernels
__global__ void zero_hist_kernel() {
    int i = blockIdx.x * blockDim.x + threadIdx.x;
    if (i < N_BUCKETS) g_hist[i] = 0u;
}

__global__ __launch_bounds__(256) void hist_kernel(const float* __restrict__ x, int N) {
    int n = blockIdx.x * 256 + threadIdx.x;
    if (n >= N) return;
    unsigned b = bucket_of(x[n * 3 + 0], x[n * 3 + 1], x[n * 3 + 2]);
    unsigned r = atomicAdd(&g_hist[b], 1u);   // rank within bucket
    g_bucket[n] = b;
    g_rank[n]   = r;
}

__global__ __launch_bounds__(1024) void scan_kernel() {
    __shared__ unsigned partial[1024];
    const int t = threadIdx.x;
    unsigned local[32];
    unsigned s = 0;
    #pragma unroll
    for (int j = 0; j < 32; ++j) { local[j] = g_hist[t * 32 + j]; s += local[j]; }
    partial[t] = s;
    __syncthreads();
    for (int d = 1; d < 1024; d <<= 1) {
        unsigned v = (t >= d) ? partial[t - d] : 0u;
        __syncthreads();
        partial[t] += v;
        __syncthreads();
    }
    unsigned run = (t > 0) ? partial[t - 1] : 0u;
    #pragma unroll
    for (int j = 0; j < 32; ++j) { g_base[t * 32 + j] = run; run += local[j]; }
}

__global__ __launch_bounds__(256) void scatter_kernel(const float* __restrict__ x, int N) {
    int n = blockIdx.x * 256 + threadIdx.x;
    if (n >= N) return;
    const unsigned pos = g_base[g_bucket[n]] + g_rank[n];   // no atomics
    g_xs[pos] = make_float4(x[n * 3 + 0], x[n * 3 + 1], x[n * 3 + 2],
                            __int_as_float(n));
}

// ------------------------------------------------------------------- main
__global__ __launch_bounds__(256) void hashgrid_kernel(
    const float2* __restrict__ table,   // [T] float2
    float4* __restrict__ out,           // [N,16] float2 viewed as [N,8] float4
    Params p, int N)
{
    const int i = blockIdx.x * 256 + threadIdx.x;
    if (i >= N) return;

    const float4 xi = g_xs[i];          // coalesced
    const float px = xi.x, py = xi.y, pz = xi.z;
    const int   n  = __float_as_int(xi.w);

    float2 acc[N_LEVELS];

    #pragma unroll
    for (int l = 0; l < N_LEVELS; ++l) {
        const float res = p.resf[l];
        const float sx = px * res;
        const float sy = py * res;
        const float sz = pz * res;

        const float fx = floorf(sx);
        const float fy = floorf(sy);
        const float fz = floorf(sz);

        const float dx = sx - fx;
        const float dy = sy - fy;
        const float dz = sz - fz;

        const unsigned x0u = (unsigned)(int)fx;
        const unsigned hy0 = (unsigned)(int)fy * P1;
        const unsigned hy1 = hy0 + P1;
        const unsigned hz0 = (unsigned)(int)fz * P2;
        const unsigned hz1 = hz0 + P2;

        const unsigned g00 = hy0 ^ hz0;
        const unsigned g10 = hy1 ^ hz0;
        const unsigned g01 = hy0 ^ hz1;
        const unsigned g11 = hy1 ^ hz1;

        const unsigned h000 = (x0u ^ g00) & T_MASK;
        const unsigned h010 = (x0u ^ g10) & T_MASK;
        const unsigned h001 = (x0u ^ g01) & T_MASK;
        const unsigned h011 = (x0u ^ g11) & T_MASK;

        const unsigned x1u  = x0u + 1u;
        const unsigned h100 = (x1u ^ g00) & T_MASK;
        const unsigned h110 = (x1u ^ g10) & T_MASK;
        const unsigned h101 = (x1u ^ g01) & T_MASK;
        const unsigned h111 = (x1u ^ g11) & T_MASK;

        const bool xeven = (x0u & 1u) == 0u;

        // 4 float4 loads always cover the x0 corners (and x1 when x0 even)
        const float4 q00 = __ldg((const float4*)&table[h000 & ~1u]);
        const float4 q10 = __ldg((const float4*)&table[h010 & ~1u]);
        const float4 q01 = __ldg((const float4*)&table[h001 & ~1u]);
        const float4 q11 = __ldg((const float4*)&table[h011 & ~1u]);

        float2 e00, e10, e01, e11;
        if (!xeven) {
            e00 = __ldg(&table[h100]);
            e10 = __ldg(&table[h110]);
            e01 = __ldg(&table[h101]);
            e11 = __ldg(&table[h111]);
        }

        const float2 q00lo = make_float2(q00.x, q00.y), q00hi = make_float2(q00.z, q00.w);
        const float2 q10lo = make_float2(q10.x, q10.y), q10hi = make_float2(q10.z, q10.w);
        const float2 q01lo = make_float2(q01.x, q01.y), q01hi = make_float2(q01.z, q01.w);
        const float2 q11lo = make_float2(q11.x, q11.y), q11hi = make_float2(q11.z, q11.w);

        const bool p00 = (h000 & 1u), p10 = (h010 & 1u), p01 = (h001 & 1u), p11 = (h011 & 1u);

        const float2 v000 = p00 ? q00hi : q00lo;
        const float2 v010 = p10 ? q10hi : q10lo;
        const float2 v001 = p01 ? q01hi : q01lo;
        const float2 v011 = p11 ? q11hi : q11lo;

        const float2 v100 = xeven ? (p00 ? q00lo : q00hi) : e00;
        const float2 v110 = xeven ? (p10 ? q10lo : q10hi) : e10;
        const float2 v101 = xeven ? (p01 ? q01lo : q01hi) : e01;
        const float2 v111 = xeven ? (p11 ? q11lo : q11hi) : e11;

        const float wx0 = 1.0f - dx, wx1 = dx;
        const float wy0 = 1.0f - dy, wy1 = dy;
        const float wz0 = 1.0f - dz, wz1 = dz;

        float a00x = v000.x * wx0 + v100.x * wx1;
        float a00y = v000.y * wx0 + v100.y * wx1;
        float a10x = v010.x * wx0 + v110.x * wx1;
        float a10y = v010.y * wx0 + v110.y * wx1;
        float a01x = v001.x * wx0 + v101.x * wx1;
        float a01y = v001.y * wx0 + v101.y * wx1;
        float a11x = v011.x * wx0 + v111.x * wx1;
        float a11y = v011.y * wx0 + v111.y * wx1;

        float b0x = a00x * wy0 + a10x * wy1;
        float b0y = a00y * wy0 + a10y * wy1;
        float b1x = a01x * wy0 + a11x * wy1;
        float b1y = a01y * wy0 + a11y * wy1;

        acc[l].x = b0x * wz0 + b1x * wz1;
        acc[l].y = b0y * wz0 + b1y * wz1;
    }

    // Store full 128B row as 8 float4 (row base 16B-aligned).
    float4* row = out + (size_t)n * 8;
    #pragma unroll
    for (int j = 0; j < 8; ++j) {
        row[j] = make_float4(acc[2 * j].x, acc[2 * j].y,
                             acc[2 * j + 1].x, acc[2 * j + 1].y);
    }
}

// ----------------------------------------------------------------- launch
extern "C" void kernel_launch(void* const* d_in, const int* in_sizes, int n_in,
                              void* d_out, int out_size)
{
    const float*  x     = (const float*)d_in[0];
    const float2* table = (const float2*)d_in[1];
    float4*       out   = (float4*)d_out;

    const int N = in_sizes[0] / 3;

    Params p;
    {
        const double growth = exp((log(128.0) - log(16.0)) / (double)(N_LEVELS - 1));
        for (int l = 0; l < N_LEVELS; ++l)
            p.resf[l] = (float)floor(16.0 * pow(growth, (double)l));
    }

    const int pb = (N + 255) / 256;

    zero_hist_kernel<<<(N_BUCKETS + 255) / 256, 256>>>();
    hist_kernel<<<pb, 256>>>(x, N);
    scan_kernel<<<1, 1024>>>();
    scatter_kernel<<<pb, 256>>>(x, N);
    hashgrid_kernel<<<pb, 256>>>(table, out, p, N);
}